// round 11
// baseline (speedup 1.0000x reference)
#include <cuda_runtime.h>
#include <math.h>

// Fixed problem shapes
#define BS     4
#define C_     64
#define H_     64
#define W_     64
#define HW     4096     // H*W
#define NPTS   4096
#define M_TOT  (BS*HW)  // 16384

#define CELL   4
#define GRIDC  16       // 64/CELL
#define NCELL  (GRIDC*GRIDC)
#define CAP    64       // max points per cell (mean 16; +12 sigma unreachable)
#define CAND3_CAP 1536  // staged 3-cell-row cap (expected ~768)

#define LRELU_SLOPE 0.1f

// ---------------- device scratch (no allocations allowed) ----------------
__device__ float  g_f3t[BS * NPTS * C_];          // feat_3d transposed [b][n][c] (4 MB)
__device__ float4 g_cellpts[BS * NCELL * CAP];    // per-cell point arrays (1 MB)
__device__ int    g_ccount[BS * NCELL];           // zeroed via memsetAsync each call

// ---------------- K1: bin (blocks 0..63) + transpose (blocks 64..1087) ----------------
__global__ void bin_transpose(const float* __restrict__ uv,
                              const float* __restrict__ f3) {
    __shared__ float tile[32][33];
    int tid = threadIdx.x;            // 256

    if (blockIdx.x < 64) {
        // ---- direct scatter binning: 1 point/thread ----
        int b     = blockIdx.x >> 4;
        int slice = blockIdx.x & 15;
        int n     = slice * 256 + tid;
        const float* uvb = uv + (size_t)b * 2 * NPTS;
        float u = uvb[n], v = uvb[NPTS + n];
        int cx = (int)(u * 0.25f);    // exact power-of-2 scale -> floor
        int cy = (int)(v * 0.25f);
        int c  = b * NCELL + cy * GRIDC + cx;
        int pos = atomicAdd(&g_ccount[c], 1);
        if (pos < CAP)
            g_cellpts[(size_t)c * CAP + pos] =
                make_float4(u, v,
                            __fadd_rn(__fmul_rn(u, u), __fmul_rn(v, v)),
                            __int_as_float(n));
        return;
    }

    // ---- transpose: 32x32 tile, float4 both ways ----
    int tix = blockIdx.x - 64;        // 0..1023
    int b   = tix >> 8;
    int rem = tix & 255;
    int c0  = (rem >> 7) * 32;
    int n0  = (rem & 127) * 32;
    const float* src = f3 + ((size_t)(b * C_ + c0)) * NPTS + n0;
    {
        int row  = tid >> 3;          // c within tile
        int col4 = tid & 7;           // float4 slot along n
        float4 v = *(const float4*)(src + row * NPTS + col4 * 4);
        tile[row][col4 * 4 + 0] = v.x;
        tile[row][col4 * 4 + 1] = v.y;
        tile[row][col4 * 4 + 2] = v.z;
        tile[row][col4 * 4 + 3] = v.w;
    }
    __syncthreads();
    float* dst = g_f3t + ((size_t)(b * NPTS + n0)) * C_ + c0;
    {
        int n    = tid >> 3;          // n within tile
        int col4 = tid & 7;           // float4 slot along c
        float4 v = make_float4(tile[col4 * 4 + 0][n],
                               tile[col4 * 4 + 1][n],
                               tile[col4 * 4 + 2][n],
                               tile[col4 * 4 + 3][n]);
        *(float4*)(dst + n * C_ + col4 * 4) = v;
    }
}

// ---------------- K2: megafused knn + score MLP + gather + out GEMM ----------------
// 256 blocks x 256 threads; block owns 64 queries = one pixel row (b, py).
// Phase A: stage cell-rows cy-1..cy+1 into smem (union region A).
// Phase B: knn, 4 threads/query, width-4 shfl merge; knn -> sKnn (smem).
//   d rounding identical to validated version:
//     cross = fma(fy, v, rn(fx*u)); d = rn(rn(g2+u2) - rn(2*cross))
//   Selection: (d, idx) lexicographic -> order-independent, matches top_k ties.
// Phase C: score (warp per 8 queries, validated shfl z-path) -> Fs (union region B).
// Phase D: register-tiled GEMM out = lrelu(w_out @ F + b_out).
#define INS(dv, iv)                                                     \
    if ((dv) < d2 || ((dv) == d2 && (iv) < i2)) {                       \
        if ((dv) < d1 || ((dv) == d1 && (iv) < i1)) {                   \
            d2 = d1; i2 = i1;                                           \
            if ((dv) < d0 || ((dv) == d0 && (iv) < i0)) {               \
                d1 = d0; i1 = i0; d0 = (dv); i0 = (iv);                 \
            } else { d1 = (dv); i1 = (iv); }                            \
        } else { d2 = (dv); i2 = (iv); }                                \
    }

union SmemU {
    struct { float4 cand[CAND3_CAP]; } A;                 // 24 KB
    struct { float Wt[64 * 64]; float Fs[64 * 64]; } B;   // 32 KB
};

__global__ void megafused(const float* __restrict__ uv,
                          const float* __restrict__ w1, const float* __restrict__ b1,
                          const float* __restrict__ w2, const float* __restrict__ b2,
                          const float* __restrict__ w_out,
                          const float* __restrict__ b_out,
                          float* __restrict__ out) {
    __shared__ SmemU smu;
    __shared__ int sCnt[48], sOff[48];
    __shared__ int sKnn[64 * 3];
    __shared__ int sTotal;

    int tid  = threadIdx.x;
    int lane = tid & 31;
    int wid  = tid >> 5;              // 8 warps
    int m0   = blockIdx.x * 64;
    int b    = blockIdx.x >> 6;       // m0 >> 12
    int py   = blockIdx.x & 63;       // (m0 >> 6) & 63
    int cy   = py >> 2;

    // ---- Phase A: stage cell-rows cy-1..cy+1 ----
    int ylo = max(cy - 1, 0), yhi = min(cy + 1, GRIDC - 1);
    int nrows = yhi - ylo + 1;
    int ncells = nrows * GRIDC;

    if (tid < ncells) {
        int y = ylo + (tid >> 4), x = tid & 15;
        int n = __ldg(&g_ccount[b * NCELL + y * GRIDC + x]);
        sCnt[tid] = (n > CAP) ? CAP : n;
    }
    __syncthreads();
    if (tid == 0) {
        int acc = 0;
        for (int k = 0; k < ncells; k++) { sOff[k] = acc; acc += sCnt[k]; }
        sTotal = acc;
    }
    __syncthreads();

    bool fits = (sTotal <= CAND3_CAP);
    if (fits) {
        for (int k = 0; k < ncells; k++) {
            int cnt = sCnt[k];
            int gbase = (b * NCELL + (ylo + (k >> 4)) * GRIDC + (k & 15)) * CAP;
            int obase = sOff[k];
            for (int i = tid; i < cnt; i += 256)
                smu.A.cand[obase + i] = g_cellpts[(size_t)gbase + i];
        }
    }
    __syncthreads();

    // ---- Phase B: knn, group g = query px, 4 threads/group ----
    {
        int g   = tid >> 2;           // 0..63 = px
        int sub = tid & 3;
        int px  = g;
        int cx  = px >> 2;
        float fx = (float)px, fy = (float)py;
        float g2 = fx * fx + fy * fy; // exact (small ints)

        float d0 = 3.4e38f, d1 = 3.4e38f, d2 = 3.4e38f;
        int   i0 = 0x7fffffff, i1 = 0x7fffffff, i2 = 0x7fffffff;

        int xlo = max(cx - 1, 0), xhi = min(cx + 1, GRIDC - 1);
        if (fits) {
            for (int ky = 0; ky < nrows; ky++)
                for (int x = xlo; x <= xhi; x++) {
                    int k = ky * 16 + x;
                    int off = sOff[k], cnt = sCnt[k];
                    for (int p = sub; p < cnt; p += 4) {
                        float4 P = smu.A.cand[off + p];
                        float cross = __fmaf_rn(fy, P.y, __fmul_rn(fx, P.x));
                        float d = __fsub_rn(__fadd_rn(g2, P.z), __fadd_rn(cross, cross));
                        int idx = __float_as_int(P.w);
                        INS(d, idx);
                    }
                }
        } else {
            // overflow slow path: never hit; gmem scan keeps correctness
            for (int y = ylo; y <= yhi; y++)
                for (int x = xlo; x <= xhi; x++) {
                    int c = b * NCELL + y * GRIDC + x;
                    int n = __ldg(&g_ccount[c]);
                    if (n > CAP) n = CAP;
                    const float4* cp = g_cellpts + (size_t)c * CAP;
                    for (int p = sub; p < n; p += 4) {
                        float4 P = cp[p];
                        float cross = __fmaf_rn(fy, P.y, __fmul_rn(fx, P.x));
                        float d = __fsub_rn(__fadd_rn(g2, P.z), __fadd_rn(cross, cross));
                        int idx = __float_as_int(P.w);
                        INS(d, idx);
                    }
                }
        }

        // merge 4 partial lists (shfl-down tree, width 4)
        #pragma unroll
        for (int off = 2; off > 0; off >>= 1) {
            float e0 = __shfl_down_sync(0xffffffffu, d0, off, 4);
            int   j0 = __shfl_down_sync(0xffffffffu, i0, off, 4);
            float e1 = __shfl_down_sync(0xffffffffu, d1, off, 4);
            int   j1 = __shfl_down_sync(0xffffffffu, i1, off, 4);
            float e2 = __shfl_down_sync(0xffffffffu, d2, off, 4);
            int   j2 = __shfl_down_sync(0xffffffffu, i2, off, 4);
            INS(e0, j0);
            INS(e1, j1);
            INS(e2, j2);
        }

        if (sub == 0) {
            // rare fallback: rings >= 2, same geometric bound (gmem)
            for (int rc = 2; rc < GRIDC; rc++) {
                float lb = (float)(CELL * (rc - 1));
                if (lb * lb > d2 + 0.5f) break;   // false while d2 = INF
                int Xlo = max(cx - rc, 0), Xhi = min(cx + rc, GRIDC - 1);
                int Ylo = max(cy - rc, 0), Yhi = min(cy + rc, GRIDC - 1);
                for (int y = Ylo; y <= Yhi; y++)
                    for (int x = Xlo; x <= Xhi; x++) {
                        if (y != cy - rc && y != cy + rc && x != cx - rc && x != cx + rc)
                            continue;             // interior already scanned
                        int c = b * NCELL + y * GRIDC + x;
                        int n = __ldg(&g_ccount[c]);
                        if (n > CAP) n = CAP;
                        const float4* cp = g_cellpts + (size_t)c * CAP;
                        for (int p = 0; p < n; p++) {
                            float4 P = cp[p];
                            float cross = __fmaf_rn(fy, P.y, __fmul_rn(fx, P.x));
                            float d = __fsub_rn(__fadd_rn(g2, P.z), __fadd_rn(cross, cross));
                            int idx = __float_as_int(P.w);
                            INS(d, idx);
                        }
                    }
            }
            sKnn[g * 3] = i0; sKnn[g * 3 + 1] = i1; sKnn[g * 3 + 2] = i2;
        }
    }
    __syncthreads();   // cand no longer needed; sKnn complete

    // ---- Phase C: stage Wt, then score (validated shfl z-path, 8 q/warp) ----
    for (int idx = tid; idx < 4096; idx += 256) {
        int o = idx >> 6, c = idx & 63;
        smu.B.Wt[c * 64 + o] = w_out[idx];
    }

    int i_mine = lane & 15;
    int j_mine = lane >> 4;
    float w1a = w1[i_mine * 3 + 0];
    float w1b = w1[i_mine * 3 + 1];
    float w1c = w1[i_mine * 3 + 2];
    float b1r = b1[i_mine];
    float w2lo[16], w2hi[16];
    #pragma unroll
    for (int i = 0; i < 16; i++) {
        w2lo[i] = w2[lane * 16 + i];
        w2hi[i] = w2[(lane + 32) * 16 + i];
    }
    float b2lo = b2[lane], b2hi = b2[lane + 32];

    #pragma unroll
    for (int t = 0; t < 8; t++) {
        int g = wid * 8 + t;               // query row within tile (0..63)
        int m = m0 + g;
        int q = m & 4095;
        float fx = (float)(q & 63);
        float fy = (float)(q >> 6);

        int n0 = sKnn[g * 3];
        int n1 = sKnn[g * 3 + 1];
        int n2 = sKnn[g * 3 + 2];
        const float* uvb = uv + (size_t)b * 2 * NPTS;

        // feature gathers (coalesced per warp; independent of MLP chain)
        const float* f0 = g_f3t + ((size_t)(b * NPTS + n0)) * C_;
        const float* f1 = g_f3t + ((size_t)(b * NPTS + n1)) * C_;
        const float* f2 = g_f3t + ((size_t)(b * NPTS + n2)) * C_;
        float f0lo = f0[lane], f0hi = f0[lane + 32];
        float f1lo = f1[lane], f1hi = f1[lane + 32];
        float f2lo = f2[lane], f2hi = f2[lane + 32];

        // h for my (i_mine, j_mine) neighbor
        int   na = j_mine ? n1 : n0;
        float ua = uvb[na], va = uvb[NPTS + na];
        float oxa = ua - fx, oya = va - fy;
        float nrma = sqrtf(oxa * oxa + oya * oya);
        float ha = fmaf(w1c, nrma, fmaf(w1b, oya, w1a * oxa)) + b1r;
        ha = ha >= 0.f ? ha : LRELU_SLOPE * ha;
        // h for (i_mine, j=2)
        float ub = uvb[n2], vb = uvb[NPTS + n2];
        float oxb = ub - fx, oyb = vb - fy;
        float nrmb = sqrtf(oxb * oxb + oyb * oyb);
        float hb = fmaf(w1c, nrmb, fmaf(w1b, oyb, w1a * oxb)) + b1r;
        hb = hb >= 0.f ? hb : LRELU_SLOPE * hb;

        float zlo0 = b2lo, zlo1 = b2lo, zlo2 = b2lo;
        float zhi0 = b2hi, zhi1 = b2hi, zhi2 = b2hi;
        #pragma unroll
        for (int i = 0; i < 16; i++) {
            float h0 = __shfl_sync(0xffffffffu, ha, i);
            float h1 = __shfl_sync(0xffffffffu, ha, 16 + i);
            float h2 = __shfl_sync(0xffffffffu, hb, i);
            zlo0 = fmaf(w2lo[i], h0, zlo0);
            zlo1 = fmaf(w2lo[i], h1, zlo1);
            zlo2 = fmaf(w2lo[i], h2, zlo2);
            zhi0 = fmaf(w2hi[i], h0, zhi0);
            zhi1 = fmaf(w2hi[i], h1, zhi1);
            zhi2 = fmaf(w2hi[i], h2, zhi2);
        }
        float s0lo = 1.f / (1.f + __expf(-zlo0));
        float s1lo = 1.f / (1.f + __expf(-zlo1));
        float s2lo = 1.f / (1.f + __expf(-zlo2));
        float s0hi = 1.f / (1.f + __expf(-zhi0));
        float s1hi = 1.f / (1.f + __expf(-zhi1));
        float s2hi = 1.f / (1.f + __expf(-zhi2));

        float flo = fmaf(s2lo, f2lo, fmaf(s1lo, f1lo, s0lo * f0lo));
        float fhi = fmaf(s2hi, f2hi, fmaf(s1hi, f1hi, s0hi * f0hi));

        smu.B.Fs[g * 64 + ((lane + g) & 63)]      = flo;
        smu.B.Fs[g * 64 + ((lane + 32 + g) & 63)] = fhi;
    }
    __syncthreads();

    // ---- Phase D: GEMM (64 rows x 64 out-channels) ----
    int mi = lane;
    int og = wid;                     // uniform per warp -> broadcast LDS for W
    float acc[2][8];
    #pragma unroll
    for (int j = 0; j < 2; j++)
        #pragma unroll
        for (int oi = 0; oi < 8; oi++) acc[j][oi] = 0.f;

    #pragma unroll 8
    for (int c = 0; c < 64; c++) {
        float4 wv0 = *(const float4*)&smu.B.Wt[c * 64 + og * 8];
        float4 wv1 = *(const float4*)&smu.B.Wt[c * 64 + og * 8 + 4];
        #pragma unroll
        for (int j = 0; j < 2; j++) {
            int r = mi + 32 * j;
            float f = smu.B.Fs[r * 64 + ((c + r) & 63)];
            acc[j][0] = fmaf(wv0.x, f, acc[j][0]);
            acc[j][1] = fmaf(wv0.y, f, acc[j][1]);
            acc[j][2] = fmaf(wv0.z, f, acc[j][2]);
            acc[j][3] = fmaf(wv0.w, f, acc[j][3]);
            acc[j][4] = fmaf(wv1.x, f, acc[j][4]);
            acc[j][5] = fmaf(wv1.y, f, acc[j][5]);
            acc[j][6] = fmaf(wv1.z, f, acc[j][6]);
            acc[j][7] = fmaf(wv1.w, f, acc[j][7]);
        }
    }
    #pragma unroll
    for (int oi = 0; oi < 8; oi++) {
        int o = og * 8 + oi;
        float bo = __ldg(&b_out[o]);
        #pragma unroll
        for (int j = 0; j < 2; j++) {
            int m = m0 + mi + 32 * j;
            int q = m & 4095;
            float v = acc[j][oi] + bo;
            v = v >= 0.f ? v : LRELU_SLOPE * v;
            out[((size_t)(b * 64 + o) << 12) + q] = v;
        }
    }
}
#undef INS

// ---------------- launch ----------------
extern "C" void kernel_launch(void* const* d_in, const int* in_sizes, int n_in,
                              void* d_out, int out_size) {
    const float* uv      = (const float*)d_in[0];
    // d_in[1] = feat_2d: shape-only in reference, unused
    const float* feat_3d = (const float*)d_in[2];
    const float* w1      = (const float*)d_in[3];
    const float* b1      = (const float*)d_in[4];
    const float* w2      = (const float*)d_in[5];
    const float* b2      = (const float*)d_in[6];
    const float* w_out   = (const float*)d_in[7];
    const float* b_out   = (const float*)d_in[8];
    float* out = (float*)d_out;

    void* ccnt_addr = nullptr;
    cudaGetSymbolAddress(&ccnt_addr, g_ccount);
    cudaMemsetAsync(ccnt_addr, 0, BS * NCELL * sizeof(int));

    bin_transpose<<<64 + 1024, 256>>>(uv, feat_3d);
    megafused<<<M_TOT / 64, 256>>>(uv, w1, b1, w2, b2, w_out, b_out, out);
}

// round 12
// speedup vs baseline: 1.3636x; 1.3636x over previous
#include <cuda_runtime.h>
#include <math.h>

// Fixed problem shapes
#define BS     4
#define C_     64
#define H_     64
#define W_     64
#define HW     4096     // H*W
#define NPTS   4096
#define M_TOT  (BS*HW)  // 16384

#define CELL   4
#define GRIDC  16       // 64/CELL
#define NCELL  (GRIDC*GRIDC)
#define CAP    64       // max points per cell (mean 16; +12 sigma unreachable)
#define CAND_CAP 640    // >= 9*CAP impossible; actual total ~144

#define LRELU_SLOPE 0.1f

// ---------------- device scratch (no allocations allowed) ----------------
__device__ float  g_f3t[BS * NPTS * C_];          // feat_3d transposed [b][n][c] (4 MB)
__device__ float4 g_cellpts[BS * NCELL * CAP];    // per-cell point arrays (1 MB)
__device__ int    g_ccount[BS * NCELL];           // zero at load; re-zeroed by K3 each call
__device__ int    g_knn[M_TOT * 3];               // knn indices

// ---------------- K1: bin (blocks 0..63) + transpose (blocks 64..1087) ----------------
__global__ void bin_transpose(const float* __restrict__ uv,
                              const float* __restrict__ f3) {
    __shared__ float tile[32][33];
    int tid = threadIdx.x;            // 256

    if (blockIdx.x < 64) {
        // ---- direct scatter binning: 1 point/thread ----
        int b     = blockIdx.x >> 4;
        int slice = blockIdx.x & 15;
        int n     = slice * 256 + tid;
        const float* uvb = uv + (size_t)b * 2 * NPTS;
        float u = uvb[n], v = uvb[NPTS + n];
        int cx = (int)(u * 0.25f);    // exact power-of-2 scale -> floor
        int cy = (int)(v * 0.25f);
        int c  = b * NCELL + cy * GRIDC + cx;
        int pos = atomicAdd(&g_ccount[c], 1);
        if (pos < CAP)
            g_cellpts[(size_t)c * CAP + pos] =
                make_float4(u, v,
                            __fadd_rn(__fmul_rn(u, u), __fmul_rn(v, v)),
                            __int_as_float(n));
        return;
    }

    // ---- transpose: 32x32 tile, float4 both ways ----
    int tix = blockIdx.x - 64;        // 0..1023
    int b   = tix >> 8;
    int rem = tix & 255;
    int c0  = (rem >> 7) * 32;
    int n0  = (rem & 127) * 32;
    const float* src = f3 + ((size_t)(b * C_ + c0)) * NPTS + n0;
    {
        int row  = tid >> 3;          // c within tile
        int col4 = tid & 7;           // float4 slot along n
        float4 v = *(const float4*)(src + row * NPTS + col4 * 4);
        tile[row][col4 * 4 + 0] = v.x;
        tile[row][col4 * 4 + 1] = v.y;
        tile[row][col4 * 4 + 2] = v.z;
        tile[row][col4 * 4 + 3] = v.w;
    }
    __syncthreads();
    float* dst = g_f3t + ((size_t)(b * NPTS + n0)) * C_ + c0;
    {
        int n    = tid >> 3;          // n within tile
        int col4 = tid & 7;           // float4 slot along c
        float4 v = make_float4(tile[col4 * 4 + 0][n],
                               tile[col4 * 4 + 1][n],
                               tile[col4 * 4 + 2][n],
                               tile[col4 * 4 + 3][n]);
        *(float4*)(dst + n * C_ + col4 * 4) = v;
    }
}

// ---------------- K2: warp-cooperative KNN ----------------
// One block per (b, cell): 16 queries, 8 threads each.
// d rounding identical to validated version:
//   cross = fma(fy, v, rn(fx*u)); d = rn(rn(g2+u2) - rn(2*cross))
// Selection: (d, idx) lexicographic -> order-independent, matches top_k ties.
#define INS(dv, iv)                                                     \
    if ((dv) < d2 || ((dv) == d2 && (iv) < i2)) {                       \
        if ((dv) < d1 || ((dv) == d1 && (iv) < i1)) {                   \
            d2 = d1; i2 = i1;                                           \
            if ((dv) < d0 || ((dv) == d0 && (iv) < i0)) {               \
                d1 = d0; i1 = i0; d0 = (dv); i0 = (iv);                 \
            } else { d1 = (dv); i1 = (iv); }                            \
        } else { d2 = (dv); i2 = (iv); }                                \
    }

__global__ void knn_search() {
    __shared__ float4 cand[CAND_CAP];

    int b    = blockIdx.x >> 8;
    int cell = blockIdx.x & 255;
    int cx = cell & (GRIDC - 1), cy = cell >> 4;
    int tid = threadIdx.x;            // 128

    // ---- gather 3x3 neighborhood cell descriptors ----
    int xlo = max(cx - 1, 0), xhi = min(cx + 1, GRIDC - 1);
    int ylo = max(cy - 1, 0), yhi = min(cy + 1, GRIDC - 1);
    int cbase[9], ccnt[9], coff[9], nc = 0, total = 0;
    for (int y = ylo; y <= yhi; y++)
        for (int x = xlo; x <= xhi; x++) {
            int c = b * NCELL + y * GRIDC + x;
            int n = __ldg(&g_ccount[c]);
            if (n > CAP) n = CAP;
            cbase[nc] = c * CAP; ccnt[nc] = n; coff[nc] = total;
            total += n; nc++;
        }

    // ---- stage into smem ----
    for (int k = 0; k < nc; k++)
        for (int i = tid; i < ccnt[k]; i += 128)
            cand[coff[k] + i] = g_cellpts[(size_t)cbase[k] + i];
    __syncthreads();

    // ---- per-query scan: group g = query, 8 threads/query ----
    int g   = tid >> 3;               // 0..15
    int sub = tid & 7;
    int px = cx * CELL + (g & 3);
    int py = cy * CELL + (g >> 2);
    float fx = (float)px, fy = (float)py;
    float g2 = fx * fx + fy * fy;     // exact (small ints)

    float d0 = 3.4e38f, d1 = 3.4e38f, d2 = 3.4e38f;
    int   i0 = 0x7fffffff, i1 = 0x7fffffff, i2 = 0x7fffffff;

    for (int p = sub; p < total; p += 8) {
        float4 P = cand[p];
        float cross = __fmaf_rn(fy, P.y, __fmul_rn(fx, P.x));
        float d = __fsub_rn(__fadd_rn(g2, P.z), __fadd_rn(cross, cross));
        int idx = __float_as_int(P.w);
        INS(d, idx);
    }

    // ---- merge 8 partial top-3 lists (shfl-down tree, width 8) ----
    #pragma unroll
    for (int off = 4; off > 0; off >>= 1) {
        float e0 = __shfl_down_sync(0xffffffffu, d0, off, 8);
        int   j0 = __shfl_down_sync(0xffffffffu, i0, off, 8);
        float e1 = __shfl_down_sync(0xffffffffu, d1, off, 8);
        int   j1 = __shfl_down_sync(0xffffffffu, i1, off, 8);
        float e2 = __shfl_down_sync(0xffffffffu, d2, off, 8);
        int   j2 = __shfl_down_sync(0xffffffffu, i2, off, 8);
        INS(e0, j0);
        INS(e1, j1);
        INS(e2, j2);
    }

    if (sub == 0) {
        // ---- rare fallback: rings >= 2, same geometric bound ----
        for (int rc = 2; rc < GRIDC; rc++) {
            float lb = (float)(CELL * (rc - 1));
            if (lb * lb > d2 + 0.5f) break;   // false while d2 = INF
            int Xlo = max(cx - rc, 0), Xhi = min(cx + rc, GRIDC - 1);
            int Ylo = max(cy - rc, 0), Yhi = min(cy + rc, GRIDC - 1);
            for (int y = Ylo; y <= Yhi; y++)
                for (int x = Xlo; x <= Xhi; x++) {
                    if (y != cy - rc && y != cy + rc && x != cx - rc && x != cx + rc)
                        continue;             // interior already scanned
                    int c = b * NCELL + y * GRIDC + x;
                    int n = __ldg(&g_ccount[c]);
                    if (n > CAP) n = CAP;
                    const float4* cp = g_cellpts + (size_t)c * CAP;
                    for (int p = 0; p < n; p++) {
                        float4 P = cp[p];
                        float cross = __fmaf_rn(fy, P.y, __fmul_rn(fx, P.x));
                        float d = __fsub_rn(__fadd_rn(g2, P.z), __fadd_rn(cross, cross));
                        int idx = __float_as_int(P.w);
                        INS(d, idx);
                    }
                }
        }
        int m = b * HW + py * 64 + px;
        g_knn[m * 3] = i0; g_knn[m * 3 + 1] = i1; g_knn[m * 3 + 2] = i2;
    }
}
#undef INS

// ---------------- K3: fused score MLP + gather + out GEMM (m-tile 64) ----------------
// 256 blocks x 256 threads; each block owns 64 queries.
// Phase 1 (per warp, 8 queries, shfl z-path): write flo/fhi into swizzled Fs.
// Phase 2: register-tiled GEMM out = lrelu(w_out @ F + b_out) from smem.
// Block 0 also re-zeroes g_ccount for the next graph replay (stream-ordered after K2).
__global__ void fused_score_gemm(const float* __restrict__ uv,
                                 const float* __restrict__ w1, const float* __restrict__ b1,
                                 const float* __restrict__ w2, const float* __restrict__ b2,
                                 const float* __restrict__ w_out,
                                 const float* __restrict__ b_out,
                                 float* __restrict__ out) {
    __shared__ float Wt[64 * 64];     // [c][o] for LDS.128 reads
    __shared__ float Fs[64 * 64];     // swizzled: row r, col (c+r)&63

    int tid  = threadIdx.x;
    int lane = tid & 31;
    int wid  = tid >> 5;              // 8 warps
    int m0   = blockIdx.x * 64;

    // reset cell counts for next call (counts already consumed by K2)
    if (blockIdx.x == 0) {
        #pragma unroll
        for (int k = 0; k < (BS * NCELL) / 256; k++)
            g_ccount[tid + k * 256] = 0;
    }

    // stage W transpose (independent of score phase)
    for (int idx = tid; idx < 4096; idx += 256) {
        int o = idx >> 6, c = idx & 63;
        Wt[c * 64 + o] = w_out[idx];
    }

    // ---- phase 1: score (shfl variant, QPW=8) ----
    int i_mine = lane & 15;
    int j_mine = lane >> 4;
    float w1a = w1[i_mine * 3 + 0];
    float w1b = w1[i_mine * 3 + 1];
    float w1c = w1[i_mine * 3 + 2];
    float b1r = b1[i_mine];
    float w2lo[16], w2hi[16];
    #pragma unroll
    for (int i = 0; i < 16; i++) {
        w2lo[i] = w2[lane * 16 + i];
        w2hi[i] = w2[(lane + 32) * 16 + i];
    }
    float b2lo = b2[lane], b2hi = b2[lane + 32];

    int base_m = m0 + wid * 8;
    #pragma unroll
    for (int t = 0; t < 8; t++) {
        int m = base_m + t;                // 0..16383
        int b = m >> 12;
        int q = m & 4095;
        float fx = (float)(q & 63);
        float fy = (float)(q >> 6);

        int n0 = __ldg(&g_knn[m * 3]);
        int n1 = __ldg(&g_knn[m * 3 + 1]);
        int n2 = __ldg(&g_knn[m * 3 + 2]);
        const float* uvb = uv + (size_t)b * 2 * NPTS;

        // feature gathers (coalesced per warp; independent of MLP chain)
        const float* f0 = g_f3t + ((size_t)(b * NPTS + n0)) * C_;
        const float* f1 = g_f3t + ((size_t)(b * NPTS + n1)) * C_;
        const float* f2 = g_f3t + ((size_t)(b * NPTS + n2)) * C_;
        float f0lo = f0[lane], f0hi = f0[lane + 32];
        float f1lo = f1[lane], f1hi = f1[lane + 32];
        float f2lo = f2[lane], f2hi = f2[lane + 32];

        // h for my (i_mine, j_mine) neighbor
        int   na = j_mine ? n1 : n0;
        float ua = uvb[na], va = uvb[NPTS + na];
        float oxa = ua - fx, oya = va - fy;
        float nrma = sqrtf(oxa * oxa + oya * oya);
        float ha = fmaf(w1c, nrma, fmaf(w1b, oya, w1a * oxa)) + b1r;
        ha = ha >= 0.f ? ha : LRELU_SLOPE * ha;
        // h for (i_mine, j=2)
        float ub = uvb[n2], vb = uvb[NPTS + n2];
        float oxb = ub - fx, oyb = vb - fy;
        float nrmb = sqrtf(oxb * oxb + oyb * oyb);
        float hb = fmaf(w1c, nrmb, fmaf(w1b, oyb, w1a * oxb)) + b1r;
        hb = hb >= 0.f ? hb : LRELU_SLOPE * hb;

        float zlo0 = b2lo, zlo1 = b2lo, zlo2 = b2lo;
        float zhi0 = b2hi, zhi1 = b2hi, zhi2 = b2hi;
        #pragma unroll
        for (int i = 0; i < 16; i++) {
            float h0 = __shfl_sync(0xffffffffu, ha, i);
            float h1 = __shfl_sync(0xffffffffu, ha, 16 + i);
            float h2 = __shfl_sync(0xffffffffu, hb, i);
            zlo0 = fmaf(w2lo[i], h0, zlo0);
            zlo1 = fmaf(w2lo[i], h1, zlo1);
            zlo2 = fmaf(w2lo[i], h2, zlo2);
            zhi0 = fmaf(w2hi[i], h0, zhi0);
            zhi1 = fmaf(w2hi[i], h1, zhi1);
            zhi2 = fmaf(w2hi[i], h2, zhi2);
        }
        float s0lo = 1.f / (1.f + __expf(-zlo0));
        float s1lo = 1.f / (1.f + __expf(-zlo1));
        float s2lo = 1.f / (1.f + __expf(-zlo2));
        float s0hi = 1.f / (1.f + __expf(-zhi0));
        float s1hi = 1.f / (1.f + __expf(-zhi1));
        float s2hi = 1.f / (1.f + __expf(-zhi2));

        float flo = fmaf(s2lo, f2lo, fmaf(s1lo, f1lo, s0lo * f0lo));
        float fhi = fmaf(s2hi, f2hi, fmaf(s1hi, f1hi, s0hi * f0hi));

        int r = wid * 8 + t;               // row within tile
        Fs[r * 64 + ((lane + r) & 63)]      = flo;
        Fs[r * 64 + ((lane + 32 + r) & 63)] = fhi;
    }
    __syncthreads();

    // ---- phase 2: GEMM (64 rows x 64 out-channels) ----
    int mi = lane;
    int og = wid;                     // uniform per warp -> broadcast LDS for W
    float acc[2][8];
    #pragma unroll
    for (int j = 0; j < 2; j++)
        #pragma unroll
        for (int oi = 0; oi < 8; oi++) acc[j][oi] = 0.f;

    #pragma unroll 8
    for (int c = 0; c < 64; c++) {
        float4 wv0 = *(const float4*)&Wt[c * 64 + og * 8];
        float4 wv1 = *(const float4*)&Wt[c * 64 + og * 8 + 4];
        #pragma unroll
        for (int j = 0; j < 2; j++) {
            int r = mi + 32 * j;
            float f = Fs[r * 64 + ((c + r) & 63)];
            acc[j][0] = fmaf(wv0.x, f, acc[j][0]);
            acc[j][1] = fmaf(wv0.y, f, acc[j][1]);
            acc[j][2] = fmaf(wv0.z, f, acc[j][2]);
            acc[j][3] = fmaf(wv0.w, f, acc[j][3]);
            acc[j][4] = fmaf(wv1.x, f, acc[j][4]);
            acc[j][5] = fmaf(wv1.y, f, acc[j][5]);
            acc[j][6] = fmaf(wv1.z, f, acc[j][6]);
            acc[j][7] = fmaf(wv1.w, f, acc[j][7]);
        }
    }
    #pragma unroll
    for (int oi = 0; oi < 8; oi++) {
        int o = og * 8 + oi;
        float bo = __ldg(&b_out[o]);
        #pragma unroll
        for (int j = 0; j < 2; j++) {
            int m = m0 + mi + 32 * j;
            int b = m >> 12;
            int q = m & 4095;
            float v = acc[j][oi] + bo;
            v = v >= 0.f ? v : LRELU_SLOPE * v;
            out[((size_t)(b * 64 + o) << 12) + q] = v;
        }
    }
}

// ---------------- launch ----------------
extern "C" void kernel_launch(void* const* d_in, const int* in_sizes, int n_in,
                              void* d_out, int out_size) {
    const float* uv      = (const float*)d_in[0];
    // d_in[1] = feat_2d: shape-only in reference, unused
    const float* feat_3d = (const float*)d_in[2];
    const float* w1      = (const float*)d_in[3];
    const float* b1      = (const float*)d_in[4];
    const float* w2      = (const float*)d_in[5];
    const float* b2      = (const float*)d_in[6];
    const float* w_out   = (const float*)d_in[7];
    const float* b_out   = (const float*)d_in[8];
    float* out = (float*)d_out;

    bin_transpose<<<64 + 1024, 256>>>(uv, feat_3d);
    knn_search<<<BS * NCELL, 128>>>();
    fused_score_gemm<<<M_TOT / 64, 256>>>(uv, w1, b1, w2, b2, w_out, b_out, out);
}